// round 16
// baseline (speedup 1.0000x reference)
#include <cuda_runtime.h>
#include <math.h>

// Problem dims
#define BB 2
#define CC 256
#define LL 4096
#define HH 8
#define DD 32
#define NBH 16
#define NPTS 65536   // 16*4096
#define KCL 256      // clusters / top_k
#define NITER 10
#define VB 128       // virtual blocks for kmeans partition
#define VBSZ 512     // points per virtual block

typedef unsigned long long ull;

// ---- packed fp32x2 helpers (per-lane IEEE rn; bit-identical to scalar ops) ----
__device__ __forceinline__ ull pk2(float lo, float hi) {
    ull r; asm("mov.b64 %0, {%1, %2};" : "=l"(r) : "f"(lo), "f"(hi)); return r;
}
__device__ __forceinline__ void upk2(ull v, float& lo, float& hi) {
    asm("mov.b64 {%0, %1}, %2;" : "=f"(lo), "=f"(hi) : "l"(v));
}
__device__ __forceinline__ ull fma2(ull a, ull b, ull c) {
    ull d; asm("fma.rn.f32x2 %0, %1, %2, %3;" : "=l"(d) : "l"(a), "l"(b), "l"(c)); return d;
}

// ---------------- scratch ----------------
__device__ float g_xc[BB*CC*LL];
__device__ float g_xq[BB*CC*LL];
__device__ float g_kv[BB*2*CC*LL];
__device__ float g_qp[BB*CC*LL];
__device__ float g_qt[NPTS*DD];
__device__ float g_kt[NPTS*DD];
__device__ float g_vt[NPTS*DD];
__device__ float g_cent[KCL*DD];
__device__ float g_cnorm[KCL];
__device__ int   g_assign[NPTS];
__device__ int   g_bcnt[VB*KCL];      // [vblock][cluster]
__device__ int   g_list[NPTS];
__device__ float g_kdist[NPTS];
__device__ int   g_topk[NBH*KCL];
__device__ float g_oin[BB*CC*LL];
__device__ float g_o2[BB*CC*LL];

// XLA:CPU-style row reduction over 32: VF4 lane partials, (s0+s2)+(s1+s3)
__device__ __forceinline__ float row_reduce_sq(const float* v) {
    float s0 = 0.f, s1 = 0.f, s2 = 0.f, s3 = 0.f;
#pragma unroll
    for (int i = 0; i < 8; i++) {
        s0 = fmaf(v[4*i+0], v[4*i+0], s0);
        s1 = fmaf(v[4*i+1], v[4*i+1], s1);
        s2 = fmaf(v[4*i+2], v[4*i+2], s2);
        s3 = fmaf(v[4*i+3], v[4*i+3], s3);
    }
    return __fadd_rn(__fadd_rn(s0, s2), __fadd_rn(s1, s3));
}

// block-wide exclusive prefix (one int per thread; blockDim mult of 32, <=512)
__device__ __forceinline__ int block_excl_scan(int v, int* wsum) {
    int lane = threadIdx.x & 31, w = threadIdx.x >> 5;
    int s = v;
#pragma unroll
    for (int o = 1; o < 32; o <<= 1) {
        int n = __shfl_up_sync(0xffffffffu, s, o);
        if (lane >= o) s += n;
    }
    if (lane == 31) wsum[w] = s;
    __syncthreads();
    int nw = blockDim.x >> 5;
    int woff = 0;
    for (int ww = 0; ww < nw; ww++) if (ww < w) woff += wsum[ww];
    return woff + s - v;
}

// ---------------- channel layer norm (both tensors in one launch; chain frozen) ----------------
__global__ void ln_kernel(const float* __restrict__ ctx,
                          const float* __restrict__ qsrc,
                          const float* __restrict__ cg, const float* __restrict__ cbta,
                          const float* __restrict__ qg, const float* __restrict__ qbta) {
    int n = blockIdx.x * blockDim.x + threadIdx.x;   // 0..16383
    int mode = n >> 13;
    int nn = n & 8191;
    const float* src   = mode ? qsrc : ctx;
    const float* gamma = mode ? qg   : cg;
    const float* beta  = mode ? qbta : cbta;
    float* dst = mode ? g_xq : g_xc;
    int b = nn >> 12, l = nn & 4095;
    const float* colp = src + (size_t)b * CC * LL + l;
    float s = 0.f;
    for (int c = 0; c < CC; c += 8) {
        float y0 = colp[(size_t)(c+0) * LL], y1 = colp[(size_t)(c+1) * LL];
        float y2 = colp[(size_t)(c+2) * LL], y3 = colp[(size_t)(c+3) * LL];
        float y4 = colp[(size_t)(c+4) * LL], y5 = colp[(size_t)(c+5) * LL];
        float y6 = colp[(size_t)(c+6) * LL], y7 = colp[(size_t)(c+7) * LL];
        s = __fadd_rn(s, y0); s = __fadd_rn(s, y1);
        s = __fadd_rn(s, y2); s = __fadd_rn(s, y3);
        s = __fadd_rn(s, y4); s = __fadd_rn(s, y5);
        s = __fadd_rn(s, y6); s = __fadd_rn(s, y7);
    }
    float mean = __fdiv_rn(s, 256.f);
    float acc = 0.f;
    for (int c = 0; c < CC; c += 8) {
        float y0 = colp[(size_t)(c+0) * LL], y1 = colp[(size_t)(c+1) * LL];
        float y2 = colp[(size_t)(c+2) * LL], y3 = colp[(size_t)(c+3) * LL];
        float y4 = colp[(size_t)(c+4) * LL], y5 = colp[(size_t)(c+5) * LL];
        float y6 = colp[(size_t)(c+6) * LL], y7 = colp[(size_t)(c+7) * LL];
        float d0 = __fsub_rn(y0, mean), d1 = __fsub_rn(y1, mean);
        float d2 = __fsub_rn(y2, mean), d3 = __fsub_rn(y3, mean);
        float d4 = __fsub_rn(y4, mean), d5 = __fsub_rn(y5, mean);
        float d6 = __fsub_rn(y6, mean), d7 = __fsub_rn(y7, mean);
        acc = fmaf(d0, d0, acc); acc = fmaf(d1, d1, acc);
        acc = fmaf(d2, d2, acc); acc = fmaf(d3, d3, acc);
        acc = fmaf(d4, d4, acc); acc = fmaf(d5, d5, acc);
        acc = fmaf(d6, d6, acc); acc = fmaf(d7, d7, acc);
    }
    float var = __fdiv_rn(acc, 256.f);
    float denom = __fadd_rn(sqrtf(var), 1e-6f);
    float* dcol = dst + (size_t)b * CC * LL + l;
    for (int c = 0; c < CC; c += 4) {
        float y0 = colp[(size_t)(c+0) * LL], y1 = colp[(size_t)(c+1) * LL];
        float y2 = colp[(size_t)(c+2) * LL], y3 = colp[(size_t)(c+3) * LL];
        dcol[(size_t)(c+0) * LL] = __fadd_rn(__fdiv_rn(__fmul_rn(gamma[c+0], __fsub_rn(y0, mean)), denom), beta[c+0]);
        dcol[(size_t)(c+1) * LL] = __fadd_rn(__fdiv_rn(__fmul_rn(gamma[c+1], __fsub_rn(y1, mean)), denom), beta[c+1]);
        dcol[(size_t)(c+2) * LL] = __fadd_rn(__fdiv_rn(__fmul_rn(gamma[c+2], __fsub_rn(y2, mean)), denom), beta[c+2]);
        dcol[(size_t)(c+3) * LL] = __fadd_rn(__fdiv_rn(__fmul_rn(gamma[c+3], __fsub_rn(y3, mean)), denom), beta[c+3]);
    }
}

// ---------------- tiled fp32 GEMM: 128x64 tile, 8x4 outputs/thread, f32x2 packed ----------------
__global__ void gemm_kernel(const float* __restrict__ W, int mode) {
    const float* X; float* Y; int M;
    if (mode == 0)      { X = g_xc;  Y = g_kv; M = 512; }
    else if (mode == 1) { X = g_xq;  Y = g_qp; M = 256; }
    else                { X = g_oin; Y = g_o2; M = 256; }

    __shared__ float As[16][136];
    __shared__ float Bs[16][64];

    int n0 = blockIdx.x * 64;
    int m0 = blockIdx.y * 128;
    int b  = n0 >> 12;
    int l0 = n0 & 4095;
    const float* Xb = X + (size_t)b * CC * LL;
    float* Yb = Y + (size_t)b * M * LL;

    int tid = threadIdx.x;
    int tx = tid & 15;
    int ty = tid >> 4;
    ull acc01[8], acc23[8];
#pragma unroll
    for (int i = 0; i < 8; i++) { acc01[i] = pk2(0.f, 0.f); acc23[i] = pk2(0.f, 0.f); }

    for (int k0 = 0; k0 < CC; k0 += 16) {
#pragma unroll
        for (int e = 0; e < 8; e++) {
            int idx = tid + e * 256;
            int i = idx >> 4, j = idx & 15;
            As[j][i] = W[(size_t)(m0 + i) * CC + k0 + j];
        }
#pragma unroll
        for (int e = 0; e < 4; e++) {
            int idx = tid + e * 256;
            int i = idx >> 6, j = idx & 63;
            Bs[i][j] = Xb[(size_t)(k0 + i) * LL + l0 + j];
        }
        __syncthreads();
#pragma unroll
        for (int kk = 0; kk < 16; kk++) {
            float a[8];
            *(float4*)a       = *(const float4*)&As[kk][ty * 8];
            *(float4*)(a + 4) = *(const float4*)&As[kk][ty * 8 + 4];
            ull b01 = *(const ull*)&Bs[kk][tx * 4];
            ull b23 = *(const ull*)&Bs[kk][tx * 4 + 2];
#pragma unroll
            for (int i = 0; i < 8; i++) {
                ull ap = pk2(a[i], a[i]);
                acc01[i] = fma2(ap, b01, acc01[i]);
                acc23[i] = fma2(ap, b23, acc23[i]);
            }
        }
        __syncthreads();
    }
#pragma unroll
    for (int i = 0; i < 8; i++) {
        float o0, o1, o2, o3;
        upk2(acc01[i], o0, o1);
        upk2(acc23[i], o2, o3);
        float4 o = make_float4(o0, o1, o2, o3);
        *(float4*)&Yb[(size_t)(m0 + ty * 8 + i) * LL + l0 + tx * 4] = o;
    }
}

// ---------------- fold (all three tensors, blockIdx.z = mode) ----------------
__global__ void fold_kernel() {
    int mode = blockIdx.z;
    const float* src; float* dst; int rows, off, doNorm;
    if (mode == 0)      { src = g_qp; dst = g_qt; rows = 256; off = 0;   doNorm = 1; }
    else if (mode == 1) { src = g_kv; dst = g_kt; rows = 512; off = 0;   doNorm = 1; }
    else                { src = g_kv; dst = g_vt; rows = 512; off = 256; doNorm = 0; }

    __shared__ float s[32][33];
    __shared__ float nrm[32];
    int bh = blockIdx.y;
    int b = bh >> 3, h = bh & 7;
    int l0 = blockIdx.x * 32;
    int x = threadIdx.x, y = threadIdx.y;

    s[y][x] = src[((size_t)b * rows + off + h * 32 + y) * LL + l0 + x];
    __syncthreads();
    if (y == 0) {
        float ss = 0.f;
#pragma unroll
        for (int d = 0; d < 32; d++) { float v = s[d][x]; ss = fmaf(v, v, ss); }
        nrm[x] = fmaxf(sqrtf(ss), 1e-12f);
    }
    __syncthreads();
    float v = s[x][y];
    if (doNorm) v = __fdiv_rn(v, nrm[y]);
    dst[((size_t)bh * LL + l0 + y) * DD + x] = v;
}

// ---------------- kmeans init ----------------
__global__ void kinit_kernel() {
    __shared__ float cs[DD];
    int j = blockIdx.x, d = threadIdx.x;
    float v = g_qt[j * DD + d];
    g_cent[j * DD + d] = v;
    cs[d] = v;
    __syncthreads();
    if (d == 0) g_cnorm[j] = row_reduce_sq(cs);
}

// ---------------- assignment: grid 128 x 512, f32x2 packed + LDS.128 centroid loads ----------------
__global__ void __launch_bounds__(512) assign_kernel(int mode) {
    __shared__ float2 sc2[(KCL/2) * DD];
    __shared__ float scn[KCL];
    __shared__ int   cnt[KCL];
    int tid = threadIdx.x;
    for (int i = tid; i < (KCL/2) * DD; i += VBSZ) {
        int jp = i >> 5, k = i & 31;
        sc2[i] = make_float2(g_cent[(2*jp) * DD + k], g_cent[(2*jp+1) * DD + k]);
    }
    if (tid < KCL) { scn[tid] = g_cnorm[tid]; cnt[tid] = 0; }
    __syncthreads();

    const float* pts = (mode == 0) ? g_qt : g_kt;
    int p = blockIdx.x * VBSZ + tid;

    float x[32];
    const float4* xp = (const float4*)(pts + (size_t)p * DD);
#pragma unroll
    for (int i = 0; i < 8; i++) ((float4*)x)[i] = xp[i];
    float xx = 0.f;
#pragma unroll
    for (int d = 0; d < 32; d++) xx = fmaf(x[d], x[d], xx);
    ull xb[32];
#pragma unroll
    for (int d = 0; d < 32; d++) xb[d] = pk2(x[d], x[d]);

    float best = 3.4e38f; int bj = 0;
    for (int j4 = 0; j4 < KCL; j4 += 4) {
        int jp = j4 >> 1;
        ull dA = pk2(0.f, 0.f), dB = pk2(0.f, 0.f);
        const ulonglong2* cA = (const ulonglong2*)(sc2 + jp * DD);        // 16B-aligned
        const ulonglong2* cB = (const ulonglong2*)(sc2 + (jp + 1) * DD);
#pragma unroll
        for (int k2 = 0; k2 < 16; k2++) {
            ulonglong2 a2 = cA[k2];
            ulonglong2 b2 = cB[k2];
            dA = fma2(xb[2*k2],     a2.x, dA);
            dA = fma2(xb[2*k2 + 1], a2.y, dA);
            dB = fma2(xb[2*k2],     b2.x, dB);
            dB = fma2(xb[2*k2 + 1], b2.y, dB);
        }
        float d0, d1, d2, d3;
        upk2(dA, d0, d1);
        upk2(dB, d2, d3);
        float s0 = __fadd_rn(__fsub_rn(xx, __fmul_rn(2.f, d0)), scn[j4]);
        float s1 = __fadd_rn(__fsub_rn(xx, __fmul_rn(2.f, d1)), scn[j4 + 1]);
        float s2 = __fadd_rn(__fsub_rn(xx, __fmul_rn(2.f, d2)), scn[j4 + 2]);
        float s3 = __fadd_rn(__fsub_rn(xx, __fmul_rn(2.f, d3)), scn[j4 + 3]);
        if (s0 < best) { best = s0; bj = j4; }
        if (s1 < best) { best = s1; bj = j4 + 1; }
        if (s2 < best) { best = s2; bj = j4 + 2; }
        if (s3 < best) { best = s3; bj = j4 + 3; }
    }
    g_assign[p] = bj;

    if (mode == 0) {
        int lane = tid & 31;
        unsigned m = __match_any_sync(0xffffffffu, bj);
        if (lane == __ffs(m) - 1) atomicAdd(&cnt[bj], __popc(m));
        __syncthreads();
        if (tid < KCL) g_bcnt[blockIdx.x * KCL + tid] = cnt[tid];
    } else {
        const float* xo = pts + (size_t)p * DD;
        const float* co = g_cent + bj * DD;
        float a0 = 0.f, a1 = 0.f, a2 = 0.f, a3 = 0.f;
#pragma unroll
        for (int i = 0; i < 8; i++) {
            a0 = __fadd_rn(a0, fabsf(__fsub_rn(co[4*i+0], xo[4*i+0])));
            a1 = __fadd_rn(a1, fabsf(__fsub_rn(co[4*i+1], xo[4*i+1])));
            a2 = __fadd_rn(a2, fabsf(__fsub_rn(co[4*i+2], xo[4*i+2])));
            a3 = __fadd_rn(a3, fabsf(__fsub_rn(co[4*i+3], xo[4*i+3])));
        }
        g_kdist[p] = __fadd_rn(__fadd_rn(a0, a2), __fadd_rn(a1, a3));
    }
}

// ---------------- scatter: grid 128 x 512; bstart/ctot/cb in-block (MLP-4 bcnt sums) ----------------
__global__ void __launch_bounds__(512) scatter_kernel() {
    __shared__ int whist[16][KCL];
    __shared__ int sbst[KCL];
    __shared__ int cb[KCL];
    __shared__ int wsum[16];
    int tid = threadIdx.x, blk = blockIdx.x;
    int w = tid >> 5, lane = tid & 31;
    for (int i = tid; i < 16 * KCL; i += VBSZ) ((int*)whist)[i] = 0;

    int run = 0, pre = 0;
    if (tid < KCL) {
        for (int vb = 0; vb < VB; vb += 4) {
            int t0 = g_bcnt[(vb+0) * KCL + tid];
            int t1 = g_bcnt[(vb+1) * KCL + tid];
            int t2 = g_bcnt[(vb+2) * KCL + tid];
            int t3 = g_bcnt[(vb+3) * KCL + tid];
            if (vb + 0 < blk) pre += t0;
            if (vb + 1 < blk) pre += t1;
            if (vb + 2 < blk) pre += t2;
            if (vb + 3 < blk) pre += t3;
            run += t0 + t1 + t2 + t3;
        }
        sbst[tid] = pre;
    }
    int excl = block_excl_scan(tid < KCL ? run : 0, wsum);
    if (tid < KCL) cb[tid] = excl;
    __syncthreads();

    int p = blk * VBSZ + tid;
    int a = g_assign[p];
    unsigned m = __match_any_sync(0xffffffffu, a);
    int rank = __popc(m & ((1u << lane) - 1u));
    if (lane == __ffs(m) - 1) whist[w][a] = __popc(m);
    __syncthreads();
    if (tid < KCL) {
        int c = tid, s = 0;
#pragma unroll
        for (int ww = 0; ww < 16; ww++) { int t = whist[ww][c]; whist[ww][c] = s; s += t; }
    }
    __syncthreads();
    int pos = cb[a] + sbst[a] + whist[w][a] + rank;
    g_list[pos] = p;
}

// ---------------- centroids: 8 clusters/block; ctot/cb in-block (MLP-4 bcnt sums) ----------------
__global__ void centroid_kernel() {   // grid 32, block 256
    __shared__ float cs[8][DD];
    __shared__ int cb[KCL];
    __shared__ int stot[KCL];
    __shared__ int wsum[16];
    int tid = threadIdx.x;
    int w = tid >> 5, d = tid & 31;

    int run = 0;
    for (int vb = 0; vb < VB; vb += 4) {
        int t0 = g_bcnt[(vb+0) * KCL + tid];
        int t1 = g_bcnt[(vb+1) * KCL + tid];
        int t2 = g_bcnt[(vb+2) * KCL + tid];
        int t3 = g_bcnt[(vb+3) * KCL + tid];
        run += t0 + t1 + t2 + t3;
    }
    stot[tid] = run;
    int excl = block_excl_scan(run, wsum);
    cb[tid] = excl;
    __syncthreads();

    int j = blockIdx.x * 8 + w;
    int base = cb[j];
    int tot  = stot[j];
    float s = 0.f;
    int i = 0;
    for (; i + 8 <= tot; i += 8) {
        int p0 = g_list[base + i + 0];
        int p1 = g_list[base + i + 1];
        int p2 = g_list[base + i + 2];
        int p3 = g_list[base + i + 3];
        int p4 = g_list[base + i + 4];
        int p5 = g_list[base + i + 5];
        int p6 = g_list[base + i + 6];
        int p7 = g_list[base + i + 7];
        float y0 = g_qt[(size_t)p0 * DD + d];
        float y1 = g_qt[(size_t)p1 * DD + d];
        float y2 = g_qt[(size_t)p2 * DD + d];
        float y3 = g_qt[(size_t)p3 * DD + d];
        float y4 = g_qt[(size_t)p4 * DD + d];
        float y5 = g_qt[(size_t)p5 * DD + d];
        float y6 = g_qt[(size_t)p6 * DD + d];
        float y7 = g_qt[(size_t)p7 * DD + d];
        s = __fadd_rn(s, y0);
        s = __fadd_rn(s, y1);
        s = __fadd_rn(s, y2);
        s = __fadd_rn(s, y3);
        s = __fadd_rn(s, y4);
        s = __fadd_rn(s, y5);
        s = __fadd_rn(s, y6);
        s = __fadd_rn(s, y7);
    }
    for (; i < tot; i++)
        s = __fadd_rn(s, g_qt[(size_t)g_list[base + i] * DD + d]);

    float old = g_cent[j * DD + d];
    float cntf = (float)tot;
    float newc = (tot > 0) ? __fdiv_rn(s, fmaxf(cntf, 1.f)) : old;
    g_cent[j * DD + d] = newc;
    cs[w][d] = newc;
    __syncwarp();
    if (d == 0) g_cnorm[j] = row_reduce_sq(cs[w]);
}

// ---------------- top-256 by k_dist (desc value, asc index) via bitonic sort ----------------
__global__ void topk_kernel() {
    __shared__ unsigned long long s[LL];
    int bh = blockIdx.x, tid = threadIdx.x;
    for (int i = tid; i < LL; i += 1024) {
        float v = g_kdist[(size_t)bh * LL + i];
        unsigned u = __float_as_uint(v);
        u = (u & 0x80000000u) ? ~u : (u | 0x80000000u);
        u = ~u;
        s[i] = ((unsigned long long)u << 32) | (unsigned)i;
    }
    __syncthreads();
    for (int k = 2; k <= LL; k <<= 1) {
        for (int j = k >> 1; j > 0; j >>= 1) {
            for (int i = tid; i < LL; i += 1024) {
                int ixj = i ^ j;
                if (ixj > i) {
                    bool up = ((i & k) == 0);
                    unsigned long long a = s[i], b = s[ixj];
                    if ((a > b) == up) { s[i] = b; s[ixj] = a; }
                }
            }
            __syncthreads();
        }
    }
    if (tid < KCL) g_topk[bh * KCL + tid] = (int)(s[tid] & 0xffffffffu);
}

// ---------------- attention: direct topk gather; no-max softmax; LDS.128 k loads ----------------
__global__ void attn_kernel() {
    __shared__ ull  kss[64 * DD];
    __shared__ float vs[128 * DD];
    __shared__ int  sidx[128];
    int bh = blockIdx.y;
    int b = bh >> 3, h = bh & 7;
    int l = blockIdx.x * 128 + threadIdx.x;

    float q[32];
    const float4* qp = (const float4*)(g_qt + ((size_t)bh * LL + l) * DD);
#pragma unroll
    for (int i = 0; i < 8; i++) ((float4*)q)[i] = qp[i];
    ull qb[32];
#pragma unroll
    for (int k = 0; k < 32; k++) qb[k] = pk2(q[k], q[k]);

    float lsum = 0.f;
    ull accp[16];
#pragma unroll
    for (int d2 = 0; d2 < 16; d2++) accp[d2] = pk2(0.f, 0.f);

    for (int c = 0; c < 2; c++) {
        __syncthreads();
        if (threadIdx.x < 128)
            sidx[threadIdx.x] = g_topk[bh * KCL + c * 128 + threadIdx.x];
        __syncthreads();
        for (int i = threadIdx.x; i < 128 * DD; i += 128) {
            int j = i >> 5, k = i & 31;
            size_t row = (size_t)bh * LL + sidx[j];
            float kvv = g_kt[row * DD + k];
            ((float*)kss)[(((j >> 1) * DD + k) << 1) | (j & 1)] = kvv;
            vs[i] = g_vt[row * DD + k];
        }
        __syncthreads();
        for (int jp = 0; jp < 64; jp++) {
            ull dp = pk2(0.f, 0.f);
            const ulonglong2* kp2 = (const ulonglong2*)(kss + jp * DD);   // 16B-aligned
#pragma unroll
            for (int k2 = 0; k2 < 16; k2++) {
                ulonglong2 kk = kp2[k2];
                dp = fma2(qb[2*k2],     kk.x, dp);
                dp = fma2(qb[2*k2 + 1], kk.y, dp);
            }
            float dot0, dot1;
            upk2(dp, dot0, dot1);
            float p0 = __expf(dot0);
            float p1 = __expf(dot1);
            lsum = __fadd_rn(__fadd_rn(lsum, p0), p1);
            ull pp0 = pk2(p0, p0), pp1 = pk2(p1, p1);
            const ulonglong2* v0 = (const ulonglong2*)(vs + (2 * jp) * DD);
            const ulonglong2* v1 = (const ulonglong2*)(vs + (2 * jp + 1) * DD);
#pragma unroll
            for (int d4 = 0; d4 < 8; d4++) {
                ulonglong2 va = v0[d4];
                ulonglong2 vb2 = v1[d4];
                accp[2*d4]     = fma2(pp0, va.x, accp[2*d4]);
                accp[2*d4 + 1] = fma2(pp0, va.y, accp[2*d4 + 1]);
                accp[2*d4]     = fma2(pp1, vb2.x, accp[2*d4]);
                accp[2*d4 + 1] = fma2(pp1, vb2.y, accp[2*d4 + 1]);
            }
        }
    }
    float inv = 1.f / lsum;
#pragma unroll
    for (int d2 = 0; d2 < 16; d2++) {
        float a0, a1;
        upk2(accp[d2], a0, a1);
        g_oin[((size_t)b * CC + h * 32 + 2*d2)     * LL + l] = a0 * inv;
        g_oin[((size_t)b * CC + h * 32 + 2*d2 + 1) * LL + l] = a1 * inv;
    }
}

// ---------------- final LN + scaled residual ----------------
__global__ void final_kernel(const float* __restrict__ qsrc,
                             const float* __restrict__ gamma,
                             const float* __restrict__ beta,
                             const float* __restrict__ gs,
                             float* __restrict__ out) {
    int n = blockIdx.x * blockDim.x + threadIdx.x;
    int b = n >> 12, l = n & 4095;
    const float* colp = g_o2 + (size_t)b * CC * LL + l;
    float s = 0.f;
    for (int c = 0; c < CC; c += 8) {
        float y0 = colp[(size_t)(c+0) * LL], y1 = colp[(size_t)(c+1) * LL];
        float y2 = colp[(size_t)(c+2) * LL], y3 = colp[(size_t)(c+3) * LL];
        float y4 = colp[(size_t)(c+4) * LL], y5 = colp[(size_t)(c+5) * LL];
        float y6 = colp[(size_t)(c+6) * LL], y7 = colp[(size_t)(c+7) * LL];
        s = __fadd_rn(s, y0); s = __fadd_rn(s, y1);
        s = __fadd_rn(s, y2); s = __fadd_rn(s, y3);
        s = __fadd_rn(s, y4); s = __fadd_rn(s, y5);
        s = __fadd_rn(s, y6); s = __fadd_rn(s, y7);
    }
    float mean = __fdiv_rn(s, 256.f);
    float acc = 0.f;
    for (int c = 0; c < CC; c += 8) {
        float y0 = colp[(size_t)(c+0) * LL], y1 = colp[(size_t)(c+1) * LL];
        float y2 = colp[(size_t)(c+2) * LL], y3 = colp[(size_t)(c+3) * LL];
        float y4 = colp[(size_t)(c+4) * LL], y5 = colp[(size_t)(c+5) * LL];
        float y6 = colp[(size_t)(c+6) * LL], y7 = colp[(size_t)(c+7) * LL];
        float d0 = __fsub_rn(y0, mean), d1 = __fsub_rn(y1, mean);
        float d2 = __fsub_rn(y2, mean), d3 = __fsub_rn(y3, mean);
        float d4 = __fsub_rn(y4, mean), d5 = __fsub_rn(y5, mean);
        float d6 = __fsub_rn(y6, mean), d7 = __fsub_rn(y7, mean);
        acc = fmaf(d0, d0, acc); acc = fmaf(d1, d1, acc);
        acc = fmaf(d2, d2, acc); acc = fmaf(d3, d3, acc);
        acc = fmaf(d4, d4, acc); acc = fmaf(d5, d5, acc);
        acc = fmaf(d6, d6, acc); acc = fmaf(d7, d7, acc);
    }
    float var = __fdiv_rn(acc, 256.f);
    float denom = __fadd_rn(sqrtf(var), 1e-6f);
    float g = gs[0];
    const float* qcol = qsrc + (size_t)b * CC * LL + l;
    float* ocol = out + (size_t)b * CC * LL + l;
    for (int c = 0; c < CC; c += 4) {
        float y0 = colp[(size_t)(c+0) * LL], y1 = colp[(size_t)(c+1) * LL];
        float y2 = colp[(size_t)(c+2) * LL], y3 = colp[(size_t)(c+3) * LL];
        float r0 = qcol[(size_t)(c+0) * LL], r1 = qcol[(size_t)(c+1) * LL];
        float r2 = qcol[(size_t)(c+2) * LL], r3 = qcol[(size_t)(c+3) * LL];
        float o0 = __fadd_rn(__fdiv_rn(__fmul_rn(gamma[c+0], __fsub_rn(y0, mean)), denom), beta[c+0]);
        float o1 = __fadd_rn(__fdiv_rn(__fmul_rn(gamma[c+1], __fsub_rn(y1, mean)), denom), beta[c+1]);
        float o2 = __fadd_rn(__fdiv_rn(__fmul_rn(gamma[c+2], __fsub_rn(y2, mean)), denom), beta[c+2]);
        float o3 = __fadd_rn(__fdiv_rn(__fmul_rn(gamma[c+3], __fsub_rn(y3, mean)), denom), beta[c+3]);
        ocol[(size_t)(c+0) * LL] = fmaf(g, o0, r0);
        ocol[(size_t)(c+1) * LL] = fmaf(g, o1, r1);
        ocol[(size_t)(c+2) * LL] = fmaf(g, o2, r2);
        ocol[(size_t)(c+3) * LL] = fmaf(g, o3, r3);
    }
}

// ---------------- launch ----------------
extern "C" void kernel_launch(void* const* d_in, const int* in_sizes, int n_in,
                              void* d_out, int out_size) {
    const float* qsrc   = (const float*)d_in[0];
    const float* ctx    = (const float*)d_in[1];
    const float* w_q    = (const float*)d_in[2];
    const float* w_kv   = (const float*)d_in[3];
    const float* w_out  = (const float*)d_in[4];
    const float* lnc_g  = (const float*)d_in[5];
    const float* lnc_b  = (const float*)d_in[6];
    const float* lnq_g  = (const float*)d_in[7];
    const float* lnq_b  = (const float*)d_in[8];
    const float* lno_g  = (const float*)d_in[9];
    const float* lno_b  = (const float*)d_in[10];
    const float* gs     = (const float*)d_in[11];
    float* out = (float*)d_out;

    ln_kernel<<<64, 256>>>(ctx, qsrc, lnc_g, lnc_b, lnq_g, lnq_b);

    gemm_kernel<<<dim3(128, 4), 256>>>(w_kv, 0);
    gemm_kernel<<<dim3(128, 2), 256>>>(w_q,  1);

    fold_kernel<<<dim3(128, NBH, 3), dim3(32, 32)>>>();

    kinit_kernel<<<KCL, 32>>>();
    for (int it = 0; it < NITER; it++) {
        assign_kernel<<<VB, VBSZ>>>(0);
        scatter_kernel<<<VB, VBSZ>>>();
        centroid_kernel<<<32, 256>>>();
    }
    assign_kernel<<<VB, VBSZ>>>(1);

    topk_kernel<<<NBH, 1024>>>();

    attn_kernel<<<dim3(32, NBH), 128>>>();

    gemm_kernel<<<dim3(128, 2), 256>>>(w_out, 2);

    final_kernel<<<32, 256>>>(qsrc, lno_g, lno_b, gs, out);
}

// round 17
// speedup vs baseline: 1.0298x; 1.0298x over previous
#include <cuda_runtime.h>
#include <math.h>

// Problem dims
#define BB 2
#define CC 256
#define LL 4096
#define HH 8
#define DD 32
#define NBH 16
#define NPTS 65536   // 16*4096
#define KCL 256      // clusters / top_k
#define NITER 10
#define VB 128       // virtual blocks for kmeans partition
#define VBSZ 512     // points per virtual block

typedef unsigned long long ull;

// ---- packed fp32x2 helpers (per-lane IEEE rn; bit-identical to scalar ops) ----
__device__ __forceinline__ ull pk2(float lo, float hi) {
    ull r; asm("mov.b64 %0, {%1, %2};" : "=l"(r) : "f"(lo), "f"(hi)); return r;
}
__device__ __forceinline__ void upk2(ull v, float& lo, float& hi) {
    asm("mov.b64 {%0, %1}, %2;" : "=f"(lo), "=f"(hi) : "l"(v));
}
__device__ __forceinline__ ull fma2(ull a, ull b, ull c) {
    ull d; asm("fma.rn.f32x2 %0, %1, %2, %3;" : "=l"(d) : "l"(a), "l"(b), "l"(c)); return d;
}

// ---------------- scratch ----------------
__device__ float g_xc[BB*CC*LL];
__device__ float g_xq[BB*CC*LL];
__device__ float g_kv[BB*2*CC*LL];
__device__ float g_qp[BB*CC*LL];
__device__ float g_qt[NPTS*DD];
__device__ float g_kt[NPTS*DD];
__device__ float g_vt[NPTS*DD];
__device__ float g_cent[KCL*DD];
__device__ float g_cnorm[KCL];
__device__ int   g_assign[NPTS];
__device__ int   g_bcnt[VB*KCL];      // [vblock][cluster]
__device__ int   g_list[NPTS];
__device__ float g_kdist[NPTS];
__device__ int   g_topk[NBH*KCL];
__device__ float g_oin[BB*CC*LL];
__device__ float g_o2[BB*CC*LL];

// XLA:CPU-style row reduction over 32: VF4 lane partials, (s0+s2)+(s1+s3)
__device__ __forceinline__ float row_reduce_sq(const float* v) {
    float s0 = 0.f, s1 = 0.f, s2 = 0.f, s3 = 0.f;
#pragma unroll
    for (int i = 0; i < 8; i++) {
        s0 = fmaf(v[4*i+0], v[4*i+0], s0);
        s1 = fmaf(v[4*i+1], v[4*i+1], s1);
        s2 = fmaf(v[4*i+2], v[4*i+2], s2);
        s3 = fmaf(v[4*i+3], v[4*i+3], s3);
    }
    return __fadd_rn(__fadd_rn(s0, s2), __fadd_rn(s1, s3));
}

// block-wide exclusive prefix (one int per thread; blockDim mult of 32, <=512)
__device__ __forceinline__ int block_excl_scan(int v, int* wsum) {
    int lane = threadIdx.x & 31, w = threadIdx.x >> 5;
    int s = v;
#pragma unroll
    for (int o = 1; o < 32; o <<= 1) {
        int n = __shfl_up_sync(0xffffffffu, s, o);
        if (lane >= o) s += n;
    }
    if (lane == 31) wsum[w] = s;
    __syncthreads();
    int nw = blockDim.x >> 5;
    int woff = 0;
    for (int ww = 0; ww < nw; ww++) if (ww < w) woff += wsum[ww];
    return woff + s - v;
}

// ---------------- channel layer norm (both tensors in one launch; chain frozen) ----------------
__global__ void ln_kernel(const float* __restrict__ ctx,
                          const float* __restrict__ qsrc,
                          const float* __restrict__ cg, const float* __restrict__ cbta,
                          const float* __restrict__ qg, const float* __restrict__ qbta) {
    int n = blockIdx.x * blockDim.x + threadIdx.x;   // 0..16383
    int mode = n >> 13;
    int nn = n & 8191;
    const float* src   = mode ? qsrc : ctx;
    const float* gamma = mode ? qg   : cg;
    const float* beta  = mode ? qbta : cbta;
    float* dst = mode ? g_xq : g_xc;
    int b = nn >> 12, l = nn & 4095;
    const float* colp = src + (size_t)b * CC * LL + l;
    float s = 0.f;
    for (int c = 0; c < CC; c += 8) {
        float y0 = colp[(size_t)(c+0) * LL], y1 = colp[(size_t)(c+1) * LL];
        float y2 = colp[(size_t)(c+2) * LL], y3 = colp[(size_t)(c+3) * LL];
        float y4 = colp[(size_t)(c+4) * LL], y5 = colp[(size_t)(c+5) * LL];
        float y6 = colp[(size_t)(c+6) * LL], y7 = colp[(size_t)(c+7) * LL];
        s = __fadd_rn(s, y0); s = __fadd_rn(s, y1);
        s = __fadd_rn(s, y2); s = __fadd_rn(s, y3);
        s = __fadd_rn(s, y4); s = __fadd_rn(s, y5);
        s = __fadd_rn(s, y6); s = __fadd_rn(s, y7);
    }
    float mean = __fdiv_rn(s, 256.f);
    float acc = 0.f;
    for (int c = 0; c < CC; c += 8) {
        float y0 = colp[(size_t)(c+0) * LL], y1 = colp[(size_t)(c+1) * LL];
        float y2 = colp[(size_t)(c+2) * LL], y3 = colp[(size_t)(c+3) * LL];
        float y4 = colp[(size_t)(c+4) * LL], y5 = colp[(size_t)(c+5) * LL];
        float y6 = colp[(size_t)(c+6) * LL], y7 = colp[(size_t)(c+7) * LL];
        float d0 = __fsub_rn(y0, mean), d1 = __fsub_rn(y1, mean);
        float d2 = __fsub_rn(y2, mean), d3 = __fsub_rn(y3, mean);
        float d4 = __fsub_rn(y4, mean), d5 = __fsub_rn(y5, mean);
        float d6 = __fsub_rn(y6, mean), d7 = __fsub_rn(y7, mean);
        acc = fmaf(d0, d0, acc); acc = fmaf(d1, d1, acc);
        acc = fmaf(d2, d2, acc); acc = fmaf(d3, d3, acc);
        acc = fmaf(d4, d4, acc); acc = fmaf(d5, d5, acc);
        acc = fmaf(d6, d6, acc); acc = fmaf(d7, d7, acc);
    }
    float var = __fdiv_rn(acc, 256.f);
    float denom = __fadd_rn(sqrtf(var), 1e-6f);
    float* dcol = dst + (size_t)b * CC * LL + l;
    for (int c = 0; c < CC; c += 4) {
        float y0 = colp[(size_t)(c+0) * LL], y1 = colp[(size_t)(c+1) * LL];
        float y2 = colp[(size_t)(c+2) * LL], y3 = colp[(size_t)(c+3) * LL];
        dcol[(size_t)(c+0) * LL] = __fadd_rn(__fdiv_rn(__fmul_rn(cg[0] == cg[0] ? gamma[c+0] : gamma[c+0], __fsub_rn(y0, mean)), denom), beta[c+0]);
        dcol[(size_t)(c+1) * LL] = __fadd_rn(__fdiv_rn(__fmul_rn(gamma[c+1], __fsub_rn(y1, mean)), denom), beta[c+1]);
        dcol[(size_t)(c+2) * LL] = __fadd_rn(__fdiv_rn(__fmul_rn(gamma[c+2], __fsub_rn(y2, mean)), denom), beta[c+2]);
        dcol[(size_t)(c+3) * LL] = __fadd_rn(__fdiv_rn(__fmul_rn(gamma[c+3], __fsub_rn(y3, mean)), denom), beta[c+3]);
    }
}

// ---------------- tiled fp32 GEMM: 128x64 tile, 8x4 outputs/thread, f32x2 packed ----------------
__global__ void gemm_kernel(const float* __restrict__ W, int mode) {
    const float* X; float* Y; int M;
    if (mode == 0)      { X = g_xc;  Y = g_kv; M = 512; }
    else if (mode == 1) { X = g_xq;  Y = g_qp; M = 256; }
    else                { X = g_oin; Y = g_o2; M = 256; }

    __shared__ float As[16][136];
    __shared__ float Bs[16][64];

    int n0 = blockIdx.x * 64;
    int m0 = blockIdx.y * 128;
    int b  = n0 >> 12;
    int l0 = n0 & 4095;
    const float* Xb = X + (size_t)b * CC * LL;
    float* Yb = Y + (size_t)b * M * LL;

    int tid = threadIdx.x;
    int tx = tid & 15;
    int ty = tid >> 4;
    ull acc01[8], acc23[8];
#pragma unroll
    for (int i = 0; i < 8; i++) { acc01[i] = pk2(0.f, 0.f); acc23[i] = pk2(0.f, 0.f); }

    for (int k0 = 0; k0 < CC; k0 += 16) {
#pragma unroll
        for (int e = 0; e < 8; e++) {
            int idx = tid + e * 256;
            int i = idx >> 4, j = idx & 15;
            As[j][i] = W[(size_t)(m0 + i) * CC + k0 + j];
        }
#pragma unroll
        for (int e = 0; e < 4; e++) {
            int idx = tid + e * 256;
            int i = idx >> 6, j = idx & 63;
            Bs[i][j] = Xb[(size_t)(k0 + i) * LL + l0 + j];
        }
        __syncthreads();
#pragma unroll
        for (int kk = 0; kk < 16; kk++) {
            float a[8];
            *(float4*)a       = *(const float4*)&As[kk][ty * 8];
            *(float4*)(a + 4) = *(const float4*)&As[kk][ty * 8 + 4];
            ull b01 = *(const ull*)&Bs[kk][tx * 4];
            ull b23 = *(const ull*)&Bs[kk][tx * 4 + 2];
#pragma unroll
            for (int i = 0; i < 8; i++) {
                ull ap = pk2(a[i], a[i]);
                acc01[i] = fma2(ap, b01, acc01[i]);
                acc23[i] = fma2(ap, b23, acc23[i]);
            }
        }
        __syncthreads();
    }
#pragma unroll
    for (int i = 0; i < 8; i++) {
        float o0, o1, o2, o3;
        upk2(acc01[i], o0, o1);
        upk2(acc23[i], o2, o3);
        float4 o = make_float4(o0, o1, o2, o3);
        *(float4*)&Yb[(size_t)(m0 + ty * 8 + i) * LL + l0 + tx * 4] = o;
    }
}

// ---------------- fold (mode = mode_base + blockIdx.z) ----------------
__global__ void fold_kernel(int mode_base) {
    int mode = mode_base + blockIdx.z;
    const float* src; float* dst; int rows, off, doNorm;
    if (mode == 0)      { src = g_qp; dst = g_qt; rows = 256; off = 0;   doNorm = 1; }
    else if (mode == 1) { src = g_kv; dst = g_kt; rows = 512; off = 0;   doNorm = 1; }
    else                { src = g_kv; dst = g_vt; rows = 512; off = 256; doNorm = 0; }

    __shared__ float s[32][33];
    __shared__ float nrm[32];
    int bh = blockIdx.y;
    int b = bh >> 3, h = bh & 7;
    int l0 = blockIdx.x * 32;
    int x = threadIdx.x, y = threadIdx.y;

    s[y][x] = src[((size_t)b * rows + off + h * 32 + y) * LL + l0 + x];
    __syncthreads();
    if (y == 0) {
        float ss = 0.f;
#pragma unroll
        for (int d = 0; d < 32; d++) { float v = s[d][x]; ss = fmaf(v, v, ss); }
        nrm[x] = fmaxf(sqrtf(ss), 1e-12f);
    }
    __syncthreads();
    float v = s[x][y];
    if (doNorm) v = __fdiv_rn(v, nrm[y]);
    dst[((size_t)bh * LL + l0 + y) * DD + x] = v;
}

// ---------------- kmeans init ----------------
__global__ void kinit_kernel() {
    __shared__ float cs[DD];
    int j = blockIdx.x, d = threadIdx.x;
    float v = g_qt[j * DD + d];
    g_cent[j * DD + d] = v;
    cs[d] = v;
    __syncthreads();
    if (d == 0) g_cnorm[j] = row_reduce_sq(cs);
}

// ---------------- assignment: grid 128 x 512 (single wave), f32x2 packed ----------------
__global__ void __launch_bounds__(512) assign_kernel(int mode) {
    __shared__ float2 sc2[(KCL/2) * DD];
    __shared__ float scn[KCL];
    __shared__ int   cnt[KCL];
    int tid = threadIdx.x;
    for (int i = tid; i < (KCL/2) * DD; i += VBSZ) {
        int jp = i >> 5, k = i & 31;
        sc2[i] = make_float2(g_cent[(2*jp) * DD + k], g_cent[(2*jp+1) * DD + k]);
    }
    if (tid < KCL) { scn[tid] = g_cnorm[tid]; cnt[tid] = 0; }
    __syncthreads();

    const float* pts = (mode == 0) ? g_qt : g_kt;
    int p = blockIdx.x * VBSZ + tid;

    float x[32];
    const float4* xp = (const float4*)(pts + (size_t)p * DD);
#pragma unroll
    for (int i = 0; i < 8; i++) ((float4*)x)[i] = xp[i];
    float xx = 0.f;
#pragma unroll
    for (int d = 0; d < 32; d++) xx = fmaf(x[d], x[d], xx);
    ull xb[32];
#pragma unroll
    for (int d = 0; d < 32; d++) xb[d] = pk2(x[d], x[d]);

    float best = 3.4e38f; int bj = 0;
    for (int j4 = 0; j4 < KCL; j4 += 4) {
        int jp = j4 >> 1;
        ull dA = pk2(0.f, 0.f), dB = pk2(0.f, 0.f);
        const ull* cA = (const ull*)(sc2 + jp * DD);
        const ull* cB = (const ull*)(sc2 + (jp + 1) * DD);
#pragma unroll
        for (int k = 0; k < 32; k++) {
            dA = fma2(xb[k], cA[k], dA);
            dB = fma2(xb[k], cB[k], dB);
        }
        float d0, d1, d2, d3;
        upk2(dA, d0, d1);
        upk2(dB, d2, d3);
        float s0 = __fadd_rn(__fsub_rn(xx, __fmul_rn(2.f, d0)), scn[j4]);
        float s1 = __fadd_rn(__fsub_rn(xx, __fmul_rn(2.f, d1)), scn[j4 + 1]);
        float s2 = __fadd_rn(__fsub_rn(xx, __fmul_rn(2.f, d2)), scn[j4 + 2]);
        float s3 = __fadd_rn(__fsub_rn(xx, __fmul_rn(2.f, d3)), scn[j4 + 3]);
        if (s0 < best) { best = s0; bj = j4; }
        if (s1 < best) { best = s1; bj = j4 + 1; }
        if (s2 < best) { best = s2; bj = j4 + 2; }
        if (s3 < best) { best = s3; bj = j4 + 3; }
    }
    g_assign[p] = bj;

    if (mode == 0) {
        int lane = tid & 31;
        unsigned m = __match_any_sync(0xffffffffu, bj);
        if (lane == __ffs(m) - 1) atomicAdd(&cnt[bj], __popc(m));
        __syncthreads();
        if (tid < KCL) g_bcnt[blockIdx.x * KCL + tid] = cnt[tid];
    } else {
        const float* xo = pts + (size_t)p * DD;
        const float* co = g_cent + bj * DD;
        float a0 = 0.f, a1 = 0.f, a2 = 0.f, a3 = 0.f;
#pragma unroll
        for (int i = 0; i < 8; i++) {
            a0 = __fadd_rn(a0, fabsf(__fsub_rn(co[4*i+0], xo[4*i+0])));
            a1 = __fadd_rn(a1, fabsf(__fsub_rn(co[4*i+1], xo[4*i+1])));
            a2 = __fadd_rn(a2, fabsf(__fsub_rn(co[4*i+2], xo[4*i+2])));
            a3 = __fadd_rn(a3, fabsf(__fsub_rn(co[4*i+3], xo[4*i+3])));
        }
        g_kdist[p] = __fadd_rn(__fadd_rn(a0, a2), __fadd_rn(a1, a3));
    }
}

// ---------------- scatter: grid 128 x 512; bstart/ctot/cb in-block ----------------
__global__ void __launch_bounds__(512) scatter_kernel() {
    __shared__ int whist[16][KCL];
    __shared__ int sbst[KCL];
    __shared__ int cb[KCL];
    __shared__ int wsum[16];
    int tid = threadIdx.x, blk = blockIdx.x;
    int w = tid >> 5, lane = tid & 31;
    for (int i = tid; i < 16 * KCL; i += VBSZ) ((int*)whist)[i] = 0;

    int run = 0, pre = 0;
    if (tid < KCL) {
        for (int vb = 0; vb < VB; vb++) {
            int t = g_bcnt[vb * KCL + tid];
            if (vb < blk) pre += t;
            run += t;
        }
        sbst[tid] = pre;
    }
    int excl = block_excl_scan(tid < KCL ? run : 0, wsum);
    if (tid < KCL) cb[tid] = excl;
    __syncthreads();

    int p = blk * VBSZ + tid;
    int a = g_assign[p];
    unsigned m = __match_any_sync(0xffffffffu, a);
    int rank = __popc(m & ((1u << lane) - 1u));
    if (lane == __ffs(m) - 1) whist[w][a] = __popc(m);
    __syncthreads();
    if (tid < KCL) {
        int c = tid, s = 0;
#pragma unroll
        for (int ww = 0; ww < 16; ww++) { int t = whist[ww][c]; whist[ww][c] = s; s += t; }
    }
    __syncthreads();
    int pos = cb[a] + sbst[a] + whist[w][a] + rank;
    g_list[pos] = p;
}

// ---------------- centroids: 8 clusters/block; ctot/cb in-block ----------------
__global__ void centroid_kernel() {   // grid 32, block 256
    __shared__ float cs[8][DD];
    __shared__ int cb[KCL];
    __shared__ int stot[KCL];
    __shared__ int wsum[16];
    int tid = threadIdx.x;
    int w = tid >> 5, d = tid & 31;

    int run = 0;
    for (int vb = 0; vb < VB; vb++) run += g_bcnt[vb * KCL + tid];
    stot[tid] = run;
    int excl = block_excl_scan(run, wsum);
    cb[tid] = excl;
    __syncthreads();

    int j = blockIdx.x * 8 + w;
    int base = cb[j];
    int tot  = stot[j];
    float s = 0.f;
    int i = 0;
    for (; i + 8 <= tot; i += 8) {
        int p0 = g_list[base + i + 0];
        int p1 = g_list[base + i + 1];
        int p2 = g_list[base + i + 2];
        int p3 = g_list[base + i + 3];
        int p4 = g_list[base + i + 4];
        int p5 = g_list[base + i + 5];
        int p6 = g_list[base + i + 6];
        int p7 = g_list[base + i + 7];
        float y0 = g_qt[(size_t)p0 * DD + d];
        float y1 = g_qt[(size_t)p1 * DD + d];
        float y2 = g_qt[(size_t)p2 * DD + d];
        float y3 = g_qt[(size_t)p3 * DD + d];
        float y4 = g_qt[(size_t)p4 * DD + d];
        float y5 = g_qt[(size_t)p5 * DD + d];
        float y6 = g_qt[(size_t)p6 * DD + d];
        float y7 = g_qt[(size_t)p7 * DD + d];
        s = __fadd_rn(s, y0);
        s = __fadd_rn(s, y1);
        s = __fadd_rn(s, y2);
        s = __fadd_rn(s, y3);
        s = __fadd_rn(s, y4);
        s = __fadd_rn(s, y5);
        s = __fadd_rn(s, y6);
        s = __fadd_rn(s, y7);
    }
    for (; i < tot; i++)
        s = __fadd_rn(s, g_qt[(size_t)g_list[base + i] * DD + d]);

    float old = g_cent[j * DD + d];
    float cntf = (float)tot;
    float newc = (tot > 0) ? __fdiv_rn(s, fmaxf(cntf, 1.f)) : old;
    g_cent[j * DD + d] = newc;
    cs[w][d] = newc;
    __syncwarp();
    if (d == 0) g_cnorm[j] = row_reduce_sq(cs[w]);
}

// ---------------- top-256 by k_dist (desc value, asc index) via bitonic sort ----------------
__global__ void topk_kernel() {
    __shared__ unsigned long long s[LL];
    int bh = blockIdx.x, tid = threadIdx.x;
    for (int i = tid; i < LL; i += 1024) {
        float v = g_kdist[(size_t)bh * LL + i];
        unsigned u = __float_as_uint(v);
        u = (u & 0x80000000u) ? ~u : (u | 0x80000000u);
        u = ~u;
        s[i] = ((unsigned long long)u << 32) | (unsigned)i;
    }
    __syncthreads();
    for (int k = 2; k <= LL; k <<= 1) {
        for (int j = k >> 1; j > 0; j >>= 1) {
            for (int i = tid; i < LL; i += 1024) {
                int ixj = i ^ j;
                if (ixj > i) {
                    bool up = ((i & k) == 0);
                    unsigned long long a = s[i], b = s[ixj];
                    if ((a > b) == up) { s[i] = b; s[ixj] = a; }
                }
            }
            __syncthreads();
        }
    }
    if (tid < KCL) g_topk[bh * KCL + tid] = (int)(s[tid] & 0xffffffffu);
}

// ---------------- attention: direct topk gather; no-max softmax ----------------
__global__ void attn_kernel() {
    __shared__ ull  kss[64 * DD];
    __shared__ float vs[128 * DD];
    __shared__ int  sidx[128];
    int bh = blockIdx.y;
    int b = bh >> 3, h = bh & 7;
    int l = blockIdx.x * 128 + threadIdx.x;

    float q[32];
    const float4* qp = (const float4*)(g_qt + ((size_t)bh * LL + l) * DD);
#pragma unroll
    for (int i = 0; i < 8; i++) ((float4*)q)[i] = qp[i];
    ull qb[32];
#pragma unroll
    for (int k = 0; k < 32; k++) qb[k] = pk2(q[k], q[k]);

    float lsum = 0.f;
    ull accp[16];
#pragma unroll
    for (int d2 = 0; d2 < 16; d2++) accp[d2] = pk2(0.f, 0.f);

    for (int c = 0; c < 2; c++) {
        __syncthreads();
        if (threadIdx.x < 128)
            sidx[threadIdx.x] = g_topk[bh * KCL + c * 128 + threadIdx.x];
        __syncthreads();
        for (int i = threadIdx.x; i < 128 * DD; i += 128) {
            int j = i >> 5, k = i & 31;
            size_t row = (size_t)bh * LL + sidx[j];
            float kvv = g_kt[row * DD + k];
            ((float*)kss)[(((j >> 1) * DD + k) << 1) | (j & 1)] = kvv;
            vs[i] = g_vt[row * DD + k];
        }
        __syncthreads();
        for (int jp = 0; jp < 64; jp++) {
            ull dp = pk2(0.f, 0.f);
            const ull* kp = kss + jp * DD;
#pragma unroll
            for (int k = 0; k < 32; k++) dp = fma2(qb[k], kp[k], dp);
            float dot0, dot1;
            upk2(dp, dot0, dot1);
            float p0 = __expf(dot0);
            float p1 = __expf(dot1);
            lsum = __fadd_rn(__fadd_rn(lsum, p0), p1);
            ull pp0 = pk2(p0, p0), pp1 = pk2(p1, p1);
            const ull* v0 = (const ull*)(vs + (2 * jp) * DD);
            const ull* v1 = (const ull*)(vs + (2 * jp + 1) * DD);
#pragma unroll
            for (int d2 = 0; d2 < 16; d2++) {
                accp[d2] = fma2(pp0, v0[d2], accp[d2]);
                accp[d2] = fma2(pp1, v1[d2], accp[d2]);
            }
        }
    }
    float inv = 1.f / lsum;
#pragma unroll
    for (int d2 = 0; d2 < 16; d2++) {
        float a0, a1;
        upk2(accp[d2], a0, a1);
        g_oin[((size_t)b * CC + h * 32 + 2*d2)     * LL + l] = a0 * inv;
        g_oin[((size_t)b * CC + h * 32 + 2*d2 + 1) * LL + l] = a1 * inv;
    }
}

// ---------------- final LN + scaled residual ----------------
__global__ void final_kernel(const float* __restrict__ qsrc,
                             const float* __restrict__ gamma,
                             const float* __restrict__ beta,
                             const float* __restrict__ gs,
                             float* __restrict__ out) {
    int n = blockIdx.x * blockDim.x + threadIdx.x;
    int b = n >> 12, l = n & 4095;
    const float* colp = g_o2 + (size_t)b * CC * LL + l;
    float s = 0.f;
    for (int c = 0; c < CC; c += 8) {
        float y0 = colp[(size_t)(c+0) * LL], y1 = colp[(size_t)(c+1) * LL];
        float y2 = colp[(size_t)(c+2) * LL], y3 = colp[(size_t)(c+3) * LL];
        float y4 = colp[(size_t)(c+4) * LL], y5 = colp[(size_t)(c+5) * LL];
        float y6 = colp[(size_t)(c+6) * LL], y7 = colp[(size_t)(c+7) * LL];
        s = __fadd_rn(s, y0); s = __fadd_rn(s, y1);
        s = __fadd_rn(s, y2); s = __fadd_rn(s, y3);
        s = __fadd_rn(s, y4); s = __fadd_rn(s, y5);
        s = __fadd_rn(s, y6); s = __fadd_rn(s, y7);
    }
    float mean = __fdiv_rn(s, 256.f);
    float acc = 0.f;
    for (int c = 0; c < CC; c += 8) {
        float y0 = colp[(size_t)(c+0) * LL], y1 = colp[(size_t)(c+1) * LL];
        float y2 = colp[(size_t)(c+2) * LL], y3 = colp[(size_t)(c+3) * LL];
        float y4 = colp[(size_t)(c+4) * LL], y5 = colp[(size_t)(c+5) * LL];
        float y6 = colp[(size_t)(c+6) * LL], y7 = colp[(size_t)(c+7) * LL];
        float d0 = __fsub_rn(y0, mean), d1 = __fsub_rn(y1, mean);
        float d2 = __fsub_rn(y2, mean), d3 = __fsub_rn(y3, mean);
        float d4 = __fsub_rn(y4, mean), d5 = __fsub_rn(y5, mean);
        float d6 = __fsub_rn(y6, mean), d7 = __fsub_rn(y7, mean);
        acc = fmaf(d0, d0, acc); acc = fmaf(d1, d1, acc);
        acc = fmaf(d2, d2, acc); acc = fmaf(d3, d3, acc);
        acc = fmaf(d4, d4, acc); acc = fmaf(d5, d5, acc);
        acc = fmaf(d6, d6, acc); acc = fmaf(d7, d7, acc);
    }
    float var = __fdiv_rn(acc, 256.f);
    float denom = __fadd_rn(sqrtf(var), 1e-6f);
    float g = gs[0];
    const float* qcol = qsrc + (size_t)b * CC * LL + l;
    float* ocol = out + (size_t)b * CC * LL + l;
    for (int c = 0; c < CC; c += 4) {
        float y0 = colp[(size_t)(c+0) * LL], y1 = colp[(size_t)(c+1) * LL];
        float y2 = colp[(size_t)(c+2) * LL], y3 = colp[(size_t)(c+3) * LL];
        float r0 = qcol[(size_t)(c+0) * LL], r1 = qcol[(size_t)(c+1) * LL];
        float r2 = qcol[(size_t)(c+2) * LL], r3 = qcol[(size_t)(c+3) * LL];
        float o0 = __fadd_rn(__fdiv_rn(__fmul_rn(gamma[c+0], __fsub_rn(y0, mean)), denom), beta[c+0]);
        float o1 = __fadd_rn(__fdiv_rn(__fmul_rn(gamma[c+1], __fsub_rn(y1, mean)), denom), beta[c+1]);
        float o2 = __fadd_rn(__fdiv_rn(__fmul_rn(gamma[c+2], __fsub_rn(y2, mean)), denom), beta[c+2]);
        float o3 = __fadd_rn(__fdiv_rn(__fmul_rn(gamma[c+3], __fsub_rn(y3, mean)), denom), beta[c+3]);
        ocol[(size_t)(c+0) * LL] = fmaf(g, o0, r0);
        ocol[(size_t)(c+1) * LL] = fmaf(g, o1, r1);
        ocol[(size_t)(c+2) * LL] = fmaf(g, o2, r2);
        ocol[(size_t)(c+3) * LL] = fmaf(g, o3, r3);
    }
}

// ---------------- launch: dual-stream DAG (kv branch hidden under kmeans) ----------------
extern "C" void kernel_launch(void* const* d_in, const int* in_sizes, int n_in,
                              void* d_out, int out_size) {
    const float* qsrc   = (const float*)d_in[0];
    const float* ctx    = (const float*)d_in[1];
    const float* w_q    = (const float*)d_in[2];
    const float* w_kv   = (const float*)d_in[3];
    const float* w_out  = (const float*)d_in[4];
    const float* lnc_g  = (const float*)d_in[5];
    const float* lnc_b  = (const float*)d_in[6];
    const float* lnq_g  = (const float*)d_in[7];
    const float* lnq_b  = (const float*)d_in[8];
    const float* lno_g  = (const float*)d_in[9];
    const float* lno_b  = (const float*)d_in[10];
    const float* gs     = (const float*)d_in[11];
    float* out = (float*)d_out;

    cudaStream_t s2;
    cudaStreamCreateWithFlags(&s2, cudaStreamNonBlocking);
    cudaEvent_t evLN, evB;
    cudaEventCreateWithFlags(&evLN, cudaEventDisableTiming);
    cudaEventCreateWithFlags(&evB,  cudaEventDisableTiming);

    // LN both inputs (main stream)
    ln_kernel<<<64, 256>>>(ctx, qsrc, lnc_g, lnc_b, lnq_g, lnq_b);
    cudaEventRecord(evLN, 0);

    // branch B on s2: kv projection + fold k/v (only needed at assign(mode1))
    cudaStreamWaitEvent(s2, evLN, 0);
    gemm_kernel<<<dim3(128, 4), 256, 0, s2>>>(w_kv, 0);
    fold_kernel<<<dim3(128, NBH, 2), dim3(32, 32), 0, s2>>>(1);   // modes 1,2
    cudaEventRecord(evB, s2);

    // main: q projection -> fold q -> kmeans
    gemm_kernel<<<dim3(128, 2), 256>>>(w_q, 1);
    fold_kernel<<<dim3(128, NBH, 1), dim3(32, 32)>>>(0);          // mode 0

    kinit_kernel<<<KCL, 32>>>();
    for (int it = 0; it < NITER; it++) {
        assign_kernel<<<VB, VBSZ>>>(0);
        scatter_kernel<<<VB, VBSZ>>>();
        centroid_kernel<<<32, 256>>>();
    }

    // join branch B, then k assignment + L1
    cudaStreamWaitEvent(0, evB, 0);
    assign_kernel<<<VB, VBSZ>>>(1);

    topk_kernel<<<NBH, 1024>>>();
    attn_kernel<<<dim3(32, NBH), 128>>>();

    gemm_kernel<<<dim3(128, 2), 256>>>(w_out, 2);
    final_kernel<<<32, 256>>>(qsrc, lno_g, lno_b, gs, out);

    cudaEventDestroy(evLN);
    cudaEventDestroy(evB);
    cudaStreamDestroy(s2);
}